// round 12
// baseline (speedup 1.0000x reference)
#include <cuda_runtime.h>
#include <cuda_bf16.h>
#include <math.h>

#define BATCH 128
#define WB 258
#define CC 33
#define NDOM 4
#define NTOT1 4198400.0
#define NTOT2 131200.0
#define NTOT3 33024.0

// ------------------- scratch -------------------
__device__ double gL[32];
__device__ double gHP[480];
__device__ double gTP[480];
__device__ double gHS[16];
__device__ double gTS[16];
__device__ double gSsum[1];
__device__ float  g_a1[16];
__device__ double g_qs[32], g_qq[32];
__device__ double g_bn3s[32], g_bn3q[32];
__device__ float  g_sdom[NDOM*CC];
__device__ float  g_cnt[NDOM];
__device__ float  g_dist2[NDOM];
__device__ volatile unsigned g_bar;
__device__ volatile unsigned g_a1flag;

// ------------------- grid barrier (all 128 blocks co-resident) -------------------
__device__ __forceinline__ void grid_barrier(unsigned target) {
    __syncthreads();
    if (threadIdx.x == 0) {
        __threadfence();
        atomicAdd((unsigned*)&g_bar, 1u);
        while (g_bar < target) { }
        __threadfence();
    }
    __syncthreads();
}

// ------------------- K0: zero accumulators -------------------
__global__ void k0_zero() {
    int t = threadIdx.x;
    for (int i = t; i < 32; i += 256) gL[i] = 0.0;
    for (int i = t; i < 480; i += 256) { gHP[i] = 0.0; gTP[i] = 0.0; }
    for (int i = t; i < 16; i += 256) { gHS[i] = 0.0; gTS[i] = 0.0; }
    if (t == 0) { gSsum[0] = 0.0; g_bar = 0u; g_a1flag = 0u; }
    for (int i = t; i < 32; i += 256) { g_qs[i]=0.0; g_qq[i]=0.0; g_bn3s[i]=0.0; g_bn3q[i]=0.0; }
    for (int i = t; i < NDOM*CC; i += 256) g_sdom[i] = 0.f;
    if (t < NDOM) { g_cnt[t] = 0.f; g_dist2[t] = 0.f; }
}

// ------------------- K1: conv1 stats via lag sums -------------------
__global__ void __launch_bounds__(256) k1_stats(const float* __restrict__ x) {
    __shared__ float xs[1056];
    int tid = threadIdx.x, lane = tid & 31, wrp = tid >> 5;
    int half = wrp & 1;
    int lg   = wrp >> 1;
    int dbase = 8 * lg;
    float accD[8];
#pragma unroll
    for (int d = 0; d < 8; d++) accD[d] = 0.f;
    float accS = 0.f;
    float accHP0=0.f, accHP1=0.f, accTP0=0.f, accTP1=0.f, accHS=0.f, accTS=0.f;

    for (int row = blockIdx.x; row < 4096; row += gridDim.x) {
        const float4* xr4 = (const float4*)(x + row * 1024);
        float4* xs4 = (float4*)xs;
        for (int i = tid; i < 264; i += 256)
            xs4[i] = (i < 256) ? xr4[i] : make_float4(0.f, 0.f, 0.f, 0.f);
        __syncthreads();
#pragma unroll
        for (int i = 0; i < 4; i++) {
            int t = 4*lane + 128*i + 512*half;
            float4 A  = *(const float4*)(xs + t);
            float4 W0 = *(const float4*)(xs + t + dbase);
            float4 W1 = *(const float4*)(xs + t + dbase + 4);
            float4 W2 = *(const float4*)(xs + t + dbase + 8);
            float a[4]  = {A.x, A.y, A.z, A.w};
            float w[12] = {W0.x,W0.y,W0.z,W0.w, W1.x,W1.y,W1.z,W1.w, W2.x,W2.y,W2.z,W2.w};
            if (lg == 0) accS += a[0] + a[1] + a[2] + a[3];
#pragma unroll
            for (int dl = 0; dl < 8; dl++)
#pragma unroll
                for (int p = 0; p < 4; p++)
                    accD[dl] = fmaf(a[p], w[p + dl], accD[dl]);
        }
        {
            int d = tid / 15, tt = tid % 15;
            accHP0 += xs[tt] * xs[tt + d];
            accTP0 += xs[1023 - d - tt] * xs[1023 - tt];
            if (tid < 224) {
                int idx = tid + 256;
                int d2 = idx / 15, t2 = idx % 15;
                accHP1 += xs[t2] * xs[t2 + d2];
                accTP1 += xs[1023 - d2 - t2] * xs[1023 - t2];
            }
        }
        if (tid < 16) { accHS += xs[tid]; accTS += xs[1023 - tid]; }
        __syncthreads();
    }
#pragma unroll
    for (int dl = 0; dl < 8; dl++) {
        float v = accD[dl];
        for (int o = 16; o > 0; o >>= 1) v += __shfl_down_sync(0xffffffffu, v, o);
        if (lane == 0) atomicAdd(&gL[dbase + dl], (double)v);
    }
    if (lg == 0) {
        float v = accS;
        for (int o = 16; o > 0; o >>= 1) v += __shfl_down_sync(0xffffffffu, v, o);
        if (lane == 0) atomicAdd(&gSsum[0], (double)v);
    }
    atomicAdd(&gHP[tid], (double)accHP0);
    atomicAdd(&gTP[tid], (double)accTP0);
    if (tid < 224) {
        atomicAdd(&gHP[tid + 256], (double)accHP1);
        atomicAdd(&gTP[tid + 256], (double)accTP1);
    }
    if (tid < 16) { atomicAdd(&gHS[tid], (double)accHS); atomicAdd(&gTS[tid], (double)accTS); }
}

// ------------------- K2: bn1 scale a1, then set ready flag -------------------
__global__ void __launch_bounds__(256) k2_bn1(const float* __restrict__ cw,
                                              const float* __restrict__ bn1w) {
    __shared__ double Tsh[32];
    __shared__ double Msh[1024];
    __shared__ double part[256];
    __shared__ double msh[16];
    int tid = threadIdx.x;
    if (tid < 32) {
        int k = tid;
        double v = gSsum[0];
        if (k <= 14) { for (int i = 0; i <= 14 - k; i++) v -= gTS[i]; }
        if (k >= 17) { for (int t = 0; t <= k - 17; t++) v -= gHS[t]; }
        Tsh[k] = v;
    }
    for (int idx = tid; idx < 1024; idx += 256) {
        int k = idx >> 5, k2 = idx & 31;
        int kl = min(k, k2), d = abs(k2 - k);
        double v = gL[d];
        if (kl >= 17) { for (int t = 0; t <= kl - 17; t++) v -= gHP[d * 15 + t]; }
        if (kl <= 14 - d) { for (int i = 0; i <= 14 - d - kl; i++) v -= gTP[d * 15 + i]; }
        Msh[idx] = v;
    }
    __syncthreads();
    if (tid < 16) {
        double m = 0.0;
        for (int k = 0; k < 32; k++) m += (double)cw[tid * 32 + k] * Tsh[k];
        msh[tid] = m / NTOT1;
    }
    {
        int o = tid >> 4, g = tid & 15;
        double p = 0.0;
#pragma unroll
        for (int kk = 2*g; kk < 2*g + 2; kk++) {
            double ck = (double)cw[o * 32 + kk];
            double inner = 0.0;
            for (int k2 = 0; k2 < 32; k2++)
                inner += (double)cw[o * 32 + k2] * Msh[kk * 32 + k2];
            p += ck * inner;
        }
        part[tid] = p;
    }
    __syncthreads();
    if (tid < 16) {
        double e2 = 0.0;
        for (int g2 = 0; g2 < 16; g2++) e2 += part[tid * 16 + g2];
        e2 /= NTOT1;
        double m = msh[tid];
        double var = e2 - m * m;
        g_a1[tid] = (float)((double)bn1w[tid] / sqrt(var + 1e-3));
    }
    __syncthreads();
    if (tid == 0) {
        __threadfence();
        atomicExch((unsigned*)&g_a1flag, 1u);
    }
}

// ------------------- KTAIL: phase0(z+conv+stats) + k6 + k7 + k9 + k10, fully fused ----------
// grid=128 (one block per batch), 512 threads, dynamic smem 183296 B
__global__ void __launch_bounds__(512) ktail(const float* __restrict__ x,
                                             const float* __restrict__ dw,
                                             const float* __restrict__ cw,
                                             const float* __restrict__ e1,
                                             const float* __restrict__ e2w,
                                             const float* __restrict__ pw,
                                             const float* __restrict__ bn2w,
                                             const float* __restrict__ bn2b,
                                             const float* __restrict__ bn3w,
                                             const float* __restrict__ bn3b,
                                             const float* __restrict__ lc1,
                                             const int* __restrict__ domains,
                                             const float* __restrict__ beta,
                                             const float* __restrict__ gamma,
                                             const float* __restrict__ mlra,
                                             const float* __restrict__ z,
                                             float* __restrict__ out) {
    extern __shared__ float sm[];
    float* qsm  = sm;
    float* zsh  = sm + 32896;
    float* dwsh = sm + 42240;
    float* cwsh = sm + 43264;
    float* we1  = sm + 43776;
    float* we2  = sm + 44288;
    float* wpp  = sm + 44800;
    float* ps   = zsh;            // stride 272, data at +8
    float* q1   = qsm;            // stride 280, data at +8
    float* q2   = qsm + 8960;     // stride 260
    float* rr   = qsm + 17280;    // stride 260
    float* lcw  = qsm + 25600;
    float* sp   = qsm + 26692;
    float* vv   = qsm + 28804;
    float* hsm  = zsh;
    float* pl   = zsh + 2112;
    __shared__ float sred[32], qred[32];
    __shared__ float s2sh[32], h2sh[32];
    __shared__ float a3[32], c3[32];
    __shared__ float mus[33], bs[33];
    __shared__ float dnv;
    __shared__ float redA[64], redB[64], redC[64];
    int tid = threadIdx.x, b = blockIdx.x;
    int dom = domains[b];
    int wrp = tid >> 5, lane = tid & 31;

    // ================= Phase 0: z = dw^T x, 32-tap conv -> q (smem), bn2 raw stats ===========
    for (int i = tid; i < 1024; i += 512) dwsh[i] = dw[i];
    for (int i = tid; i < 512; i += 512) cwsh[i] = cw[i];
    if (tid < 32) { sred[tid] = 0.f; qred[tid] = 0.f; }
    __syncthreads();
    {
        int og = (wrp & 3) * 8;   // 8-channel group
        int th = wrp >> 2;        // position quarter 0..3
        const float* xb = x + b * 32768;
        for (int c = 0; c < 4; c++) {
            int base = c * 256 - 16;
            float acc[3][8];
#pragma unroll
            for (int j = 0; j < 3; j++)
#pragma unroll
                for (int q = 0; q < 8; q++) acc[j][q] = 0.f;
            for (int h = 0; h < 32; h++) {
                float dwreg[8];
#pragma unroll
                for (int q = 0; q < 8; q++) dwreg[q] = dwsh[(og + q)*32 + h];
                const float* xh = xb + h * 1024;
#pragma unroll
                for (int j = 0; j < 3; j++) {
                    int tl = lane + 32*th + 128*j;
                    int t = base + tl;
                    float xv = (tl < 288 && (unsigned)t < 1024u) ? xh[t] : 0.f;
#pragma unroll
                    for (int q = 0; q < 8; q++) acc[j][q] = fmaf(dwreg[q], xv, acc[j][q]);
                }
            }
#pragma unroll
            for (int j = 0; j < 3; j++) {
                int tl = lane + 32*th + 128*j;
                if (tl < 288)
#pragma unroll
                    for (int q = 0; q < 8; q++) zsh[(og+q)*292 + tl] = acc[j][q];
            }
            __syncthreads();
            for (int r = 0; r < 2; r++) {
                int o2 = wrp + 16*r;
                float cwreg[32];
#pragma unroll
                for (int k = 0; k < 32; k++) cwreg[k] = cwsh[(o2 >> 1)*32 + k];
                const float* zrow = zsh + o2*292;
                float* qrow = qsm + o2*1028 + c*256;
                float psum = 0.f, pq = 0.f;
#pragma unroll
                for (int m = 0; m < 2; m++) {
                    int wl4 = 4*lane + 128*m;
                    float wbuf[8];
                    float4 v0 = *(const float4*)(zrow + wl4);
                    float4 v1 = *(const float4*)(zrow + wl4 + 4);
                    wbuf[0]=v0.x; wbuf[1]=v0.y; wbuf[2]=v0.z; wbuf[3]=v0.w;
                    wbuf[4]=v1.x; wbuf[5]=v1.y; wbuf[6]=v1.z; wbuf[7]=v1.w;
                    float a0=0.f, a1v=0.f, a2v=0.f, a3v=0.f;
#pragma unroll
                    for (int k4 = 0; k4 < 8; k4++) {
#pragma unroll
                        for (int kk = 0; kk < 4; kk++) {
                            float cv = cwreg[4*k4 + kk];
                            a0  = fmaf(cv, wbuf[kk],   a0);
                            a1v = fmaf(cv, wbuf[kk+1], a1v);
                            a2v = fmaf(cv, wbuf[kk+2], a2v);
                            a3v = fmaf(cv, wbuf[kk+3], a3v);
                        }
                        if (k4 < 7) {
                            float4 nv = *(const float4*)(zrow + wl4 + 4*k4 + 8);
                            wbuf[0]=wbuf[4]; wbuf[1]=wbuf[5]; wbuf[2]=wbuf[6]; wbuf[3]=wbuf[7];
                            wbuf[4]=nv.x; wbuf[5]=nv.y; wbuf[6]=nv.z; wbuf[7]=nv.w;
                        }
                    }
                    *(float4*)(qrow + wl4) = make_float4(a0, a1v, a2v, a3v);
                    psum += a0 + a1v + a2v + a3v;
                    pq   += a0*a0 + a1v*a1v + a2v*a2v + a3v*a3v;
                }
                for (int o = 16; o > 0; o >>= 1) {
                    psum += __shfl_down_sync(0xffffffffu, psum, o);
                    pq   += __shfl_down_sync(0xffffffffu, pq, o);
                }
                if (lane == 0) { atomicAdd(&sred[o2], psum); atomicAdd(&qred[o2], pq); }
            }
            if (c == 3 && tid < 32) {
                int o2 = tid;
                float y = 0.f;
                for (int k = 0; k < 32; k++) y += cwsh[(o2>>1)*32 + k] * zsh[o2*292 + 256 + k];
                qsm[o2*1028 + 1024] = y;
                atomicAdd(&sred[o2], y); atomicAdd(&qred[o2], y*y);
            }
            __syncthreads();
        }
    }
    if (tid < 32) {
        atomicAdd(&g_qs[tid], (double)sred[tid]);
        atomicAdd(&g_qq[tid], (double)qred[tid]);
    }
    grid_barrier(128u);
    // wait for k2's bn1 coefficient (side stream)
    if (tid == 0) { while (g_a1flag == 0u) { } __threadfence(); }
    __syncthreads();

    // ================= Phase A: bn2-affine + elu + pool + ec1 + b2c1 + b2c2 + bn3 stats ======
    for (int i = tid; i < 512; i += 512) { we1[i] = e1[i]; we2[i] = e2w[i]; }
    for (int i = tid; i < 1024; i += 512) wpp[i] = pw[i];
    if (tid < 32) {
        double mq = g_qs[tid] / NTOT2;
        double vq = g_qq[tid] / NTOT2 - mq*mq;
        double a1 = (double)g_a1[tid >> 1];
        double sc = a1 * (double)bn2w[tid] / sqrt(a1*a1*vq + 1e-3);
        s2sh[tid] = (float)sc;
        h2sh[tid] = (float)((double)bn2b[tid] - mq*sc);
    }
    // zero ps edge pads (row stride 272: pads [0,8) and [264,272))  -- FIXED index
    __syncthreads();
    for (int i = tid; i < 32*16; i += 512) {
        int o = i >> 4, k = i & 15;
        ps[o*272 + ((k < 8) ? k : 256 + k)] = 0.f;   // 0..7 and 264..271
    }
    __syncthreads();
    for (int i = tid; i < 8192; i += 512) {
        int o = i >> 8, w = i & 255;
        float sc = s2sh[o], sh = h2sh[o];
        float4 v = *(const float4*)(qsm + o*1028 + 4*w);
        float vl[4] = {v.x, v.y, v.z, v.w};
        float s = 0.f;
#pragma unroll
        for (int j = 0; j < 4; j++) {
            float y = fmaf(sc, vl[j], sh);
            s += (y > 0.f) ? y : expm1f(y);
        }
        ps[o*272 + 8 + w] = s * 0.25f;
    }
    __syncthreads();
    // zero q1 pads (stride 280: [0,8) and [265,281))
    for (int i = tid; i < 32*24; i += 512) {
        int o = i / 24, k = i % 24;
        q1[o*280 + ((k < 8) ? k : 257 + k)] = 0.f;   // 0..7 and 265..280
    }
    __syncthreads();
    // conv1: w in [0,257)
    for (int g = tid; g < 2080; g += 512) {
        int o = g / 65, w4 = (g - o*65) * 4;
        const float* prow = ps + o*272 + w4;
        float wbuf[8];
        float4 v0 = *(const float4*)(prow);
        float4 v1 = *(const float4*)(prow + 4);
        wbuf[0]=v0.x; wbuf[1]=v0.y; wbuf[2]=v0.z; wbuf[3]=v0.w;
        wbuf[4]=v1.x; wbuf[5]=v1.y; wbuf[6]=v1.z; wbuf[7]=v1.w;
        float a0=0.f,a1=0.f,a2=0.f,a3v=0.f;
#pragma unroll
        for (int k4 = 0; k4 < 4; k4++) {
#pragma unroll
            for (int kk = 0; kk < 4; kk++) {
                float wv = we1[o*16 + 4*k4 + kk];
                a0  = fmaf(wv, wbuf[kk],   a0);
                a1  = fmaf(wv, wbuf[kk+1], a1);
                a2  = fmaf(wv, wbuf[kk+2], a2);
                a3v = fmaf(wv, wbuf[kk+3], a3v);
            }
            if (k4 < 3) {
                float4 nv = *(const float4*)(prow + 8 + 4*k4);
                wbuf[0]=wbuf[4]; wbuf[1]=wbuf[5]; wbuf[2]=wbuf[6]; wbuf[3]=wbuf[7];
                wbuf[4]=nv.x; wbuf[5]=nv.y; wbuf[6]=nv.z; wbuf[7]=nv.w;
            }
        }
        float* q1r = q1 + o*280 + 8 + w4;
        if (w4     < 257) q1r[0] = a0;
        if (w4 + 1 < 257) q1r[1] = a1;
        if (w4 + 2 < 257) q1r[2] = a2;
        if (w4 + 3 < 257) q1r[3] = a3v;
    }
    __syncthreads();
    // conv2: w in [0,258)
    for (int g = tid; g < 2080; g += 512) {
        int o = g / 65, w4 = (g - o*65) * 4;
        const float* prow = q1 + o*280 + w4;
        float wbuf[8];
        float4 v0 = *(const float4*)(prow);
        float4 v1 = *(const float4*)(prow + 4);
        wbuf[0]=v0.x; wbuf[1]=v0.y; wbuf[2]=v0.z; wbuf[3]=v0.w;
        wbuf[4]=v1.x; wbuf[5]=v1.y; wbuf[6]=v1.z; wbuf[7]=v1.w;
        float a0=0.f,a1=0.f,a2=0.f,a3v=0.f;
#pragma unroll
        for (int k4 = 0; k4 < 4; k4++) {
#pragma unroll
            for (int kk = 0; kk < 4; kk++) {
                float wv = we2[o*16 + 4*k4 + kk];
                a0  = fmaf(wv, wbuf[kk],   a0);
                a1  = fmaf(wv, wbuf[kk+1], a1);
                a2  = fmaf(wv, wbuf[kk+2], a2);
                a3v = fmaf(wv, wbuf[kk+3], a3v);
            }
            if (k4 < 3) {
                float4 nv = *(const float4*)(prow + 8 + 4*k4);
                wbuf[0]=wbuf[4]; wbuf[1]=wbuf[5]; wbuf[2]=wbuf[6]; wbuf[3]=wbuf[7];
                wbuf[4]=nv.x; wbuf[5]=nv.y; wbuf[6]=nv.z; wbuf[7]=nv.w;
            }
        }
        float* q2r = q2 + o*260 + w4;
        if (w4     < 258) q2r[0] = a0;
        if (w4 + 1 < 258) q2r[1] = a1;
        if (w4 + 2 < 258) q2r[2] = a2;
        if (w4 + 3 < 258) q2r[3] = a3v;
    }
    __syncthreads();
    // pointwise 32x32: 2 output channels per thread
    {
        int o = tid >> 5;
        int wslot = tid & 31;
        float ls0=0.f, lq0=0.f, ls1=0.f, lq1=0.f;
        for (int it = 0; it < 3; it++) {
            int w4 = 4*(wslot + 32*it);
            if (w4 > 256) continue;
            float a0=0.f,a1=0.f,a2=0.f,a3v=0.f;
            float b0=0.f,b1=0.f,b2=0.f,b3=0.f;
#pragma unroll 8
            for (int c = 0; c < 32; c++) {
                float4 qv = *(const float4*)(q2 + c*260 + w4);
                float w1 = wpp[o*32 + c];
                float w2 = wpp[(o+16)*32 + c];
                a0  = fmaf(w1, qv.x, a0);
                a1  = fmaf(w1, qv.y, a1);
                a2  = fmaf(w1, qv.z, a2);
                a3v = fmaf(w1, qv.w, a3v);
                b0  = fmaf(w2, qv.x, b0);
                b1  = fmaf(w2, qv.y, b1);
                b2  = fmaf(w2, qv.z, b2);
                b3  = fmaf(w2, qv.w, b3);
            }
            float* r0 = rr + o*260 + w4;
            float* r1 = rr + (o+16)*260 + w4;
            int nv = WB - w4;
            if (nv > 0) { r0[0]=a0;  r1[0]=b0; ls0+=a0;  lq0+=a0*a0;   ls1+=b0; lq1+=b0*b0; }
            if (nv > 1) { r0[1]=a1;  r1[1]=b1; ls0+=a1;  lq0+=a1*a1;   ls1+=b1; lq1+=b1*b1; }
            if (nv > 2) { r0[2]=a2;  r1[2]=b2; ls0+=a2;  lq0+=a2*a2;   ls1+=b2; lq1+=b2*b2; }
            if (nv > 3) { r0[3]=a3v; r1[3]=b3; ls0+=a3v; lq0+=a3v*a3v; ls1+=b3; lq1+=b3*b3; }
        }
        for (int d = 16; d > 0; d >>= 1) {
            ls0 += __shfl_down_sync(0xffffffffu, ls0, d);
            lq0 += __shfl_down_sync(0xffffffffu, lq0, d);
            ls1 += __shfl_down_sync(0xffffffffu, ls1, d);
            lq1 += __shfl_down_sync(0xffffffffu, lq1, d);
        }
        if (wslot == 0) {
            atomicAdd(&g_bn3s[o],      (double)ls0);
            atomicAdd(&g_bn3q[o],      (double)lq0);
            atomicAdd(&g_bn3s[o + 16], (double)ls1);
            atomicAdd(&g_bn3q[o + 16], (double)lq1);
        }
    }
    grid_barrier(256u);

    // ================= Phase B: bn3+elu+pool+normalize+lift -> pts (sp), domain sums =========
    for (int i = tid; i < 1089; i += 512) lcw[i] = lc1[i];
    if (tid < 32) {
        double mean = g_bn3s[tid] / NTOT3;
        double var = g_bn3q[tid] / NTOT3 - mean * mean;
        float a = (float)((double)bn3w[tid] / sqrt(var + 1e-3));
        a3[tid] = a;
        c3[tid] = (float)((double)bn3b[tid] - mean * (double)a);
    }
    __syncthreads();
    for (int t = tid; t < 2048; t += 512) {
        int w = t >> 5, c = t & 31;
        const float* rb = rr + c * 260 + w * 4;
        float acc = 0.f;
#pragma unroll
        for (int i = 0; i < 4; i++) {
            float v = a3[c] * rb[i] + c3[c];
            acc += (v > 0.f) ? v : expm1f(v);
        }
        vv[w * 33 + c] = acc * 0.25f;
    }
    __syncthreads();
    if (tid < 64) {
        int w = tid;
        float ssq = 0.f;
        for (int c = 0; c < 32; c++) { float sv = vv[w*33+c]; ssq += sv * sv; }
        float inv = 1.f / fmaxf(sqrtf(ssq), 1e-12f);
        float hs2 = 0.f;
        for (int c = 0; c < 32; c++) { float sv = vv[w*33+c] * inv; vv[w*33+c] = sv; hs2 += sv * sv; }
        vv[w * 33 + 32] = sqrtf(1.f + hs2);
    }
    __syncthreads();
    for (int t = tid; t < 2048; t += 512) {
        int w = t >> 5, o = (t & 31) + 1;
        float acc = lcw[o * 33] * vv[w * 33 + 32];
#pragma unroll
        for (int c = 0; c < 32; c++) acc = fmaf(lcw[o * 33 + 1 + c], vv[w * 33 + c], acc);
        sp[w * 33 + o] = acc;
    }
    __syncthreads();
    if (tid < 64) {
        float ysq = 0.f;
        for (int o = 1; o < 33; o++) { float pv = sp[tid*33+o]; ysq += pv * pv; }
        sp[tid * 33] = sqrtf(1.f + ysq);
    }
    __syncthreads();
    if (tid < 33) {
        float acc = 0.f;
        for (int ww = 0; ww < 64; ww++) acc += sp[ww * 33 + tid];
        atomicAdd(&g_sdom[dom * 33 + tid], acc);
    }
    if (tid == 0) atomicAdd(&g_cnt[dom], 64.f);
    grid_barrier(384u);

    // ================= Phase C: mu + log-map + transport, dist^2 =============================
    if (tid < 33) {
        float cnt = fmaxf(g_cnt[dom], 1.f);
        mus[tid] = g_sdom[dom * 33 + tid] / cnt;
    }
    __syncthreads();
    if (tid == 0) {
        float mm = -mus[0] * mus[0];
        for (int j = 1; j < 33; j++) mm += mus[j] * mus[j];
        dnv = sqrtf(fmaxf(fabsf(mm), 1e-8f));
    }
    __syncthreads();
    if (tid < 33) mus[tid] = mus[tid] / dnv;
    __syncthreads();
    if (tid < 64) {
        float p[33];
        for (int j = 0; j < 33; j++) p[j] = sp[tid * 33 + j];
        float ip = -mus[0] * p[0];
        for (int j = 1; j < 33; j++) ip += mus[j] * p[j];
        float ci = fmaxf(-ip, 1.f + 1e-7f);
        float dist = acoshf(ci);
        float u[33];
        for (int j = 0; j < 33; j++) u[j] = p[j] + ip * mus[j];
        float muu = -u[0] * u[0];
        for (int j = 1; j < 33; j++) muu += u[j] * u[j];
        float un = sqrtf(fmaxf(muu, 1e-8f));
        float sc = dist / un;
        float v0 = sc * u[0];
        float f = -v0 / (1.f + mus[0]);
        vv[tid * 33 + 0] = v0 + f * (mus[0] + 1.f);
        for (int j = 1; j < 33; j++) vv[tid * 33 + j] = sc * u[j] + f * mus[j];
        redA[tid] = dist * dist;
    }
    __syncthreads();
    if (tid == 0) {
        float s = 0.f;
        for (int i = 0; i < 64; i++) s += redA[i];
        atomicAdd(&g_dist2[dom], s);
    }
    grid_barrier(512u);

    // ================= Phase D: scale + beta transport + exp-map + elu + pool + out ==========
    if (tid < 33) bs[tid] = beta[tid];
    __syncthreads();
    if (tid < 64) {
        float cnt = fmaxf(g_cnt[dom], 1.f);
        float var = g_dist2[dom] / cnt;
        float scale = gamma[0] / sqrtf(var + 1e-5f);
        float v[33];
        for (int j = 0; j < 33; j++) v[j] = vv[tid * 33 + j] * scale;
        float mb = -bs[0] * v[0];
        for (int j = 1; j < 33; j++) mb += bs[j] * v[j];
        float f = mb / (1.f + bs[0]);
        v[0] += f * (1.f + bs[0]);
        for (int j = 1; j < 33; j++) v[j] += f * bs[j];
        float mv = -v[0] * v[0];
        for (int j = 1; j < 33; j++) mv += v[j] * v[j];
        float vn = sqrtf(fmaxf(mv, 1e-8f));
        float ch = coshf(vn), sh = sinhf(vn) / vn;
        float ssum = 0.f;
        float sv[33];
        for (int j = 1; j < 33; j++) {
            float y = ch * bs[j] + sh * v[j];
            float e = (y > 0.f) ? y : expm1f(y);
            sv[j] = e;
            ssum += e * e;
        }
        hsm[tid * 33 + 0] = sqrtf(1.f + ssum);
        for (int j = 1; j < 33; j++) hsm[tid * 33 + j] = sv[j];
    }
    __syncthreads();
    if (tid < 16) {
        float m[33];
        for (int j = 0; j < 33; j++) {
            m[j] = 0.25f * (hsm[(4 * tid) * 33 + j] + hsm[(4 * tid + 1) * 33 + j] +
                            hsm[(4 * tid + 2) * 33 + j] + hsm[(4 * tid + 3) * 33 + j]);
        }
        float mm = -m[0] * m[0];
        for (int j = 1; j < 33; j++) mm += m[j] * m[j];
        float dnm = sqrtf(fmaxf(fabsf(mm), 1e-8f));
        for (int j = 0; j < 33; j++) pl[tid * 33 + j] = m[j] / dnm;
    }
    __syncthreads();
    if (tid < 64) {
        float pssq = 0.f, pdot = 0.f, pz2 = 0.f;
        for (int i = tid; i < 512; i += 64) {
            int g = i >> 5, j = (i & 31) + 1;
            float fv = pl[g * 33 + j];
            out[128 + b * 513 + 1 + i] = fv;
            float zv = z[i];
            pssq += fv * fv;
            pdot += fv * zv;
            pz2  += zv * zv;
        }
        redA[tid] = pssq;
        redB[tid] = pdot;
        redC[tid] = pz2;
    }
    __syncthreads();
    if (tid == 0) {
        float ssq = 0.f, dot = 0.f, z2 = 0.f;
        for (int i = 0; i < 64; i++) { ssq += redA[i]; dot += redB[i]; z2 += redC[i]; }
        float ft = sqrtf(1.f + ssq);
        out[128 + b * 513] = ft;
        float a = mlra[0], nz = sqrtf(z2);
        float wt = sinhf(a) * nz;
        float cz = coshf(a) * nz;
        float bet = sqrtf(fmaxf(cz * cz - wt * wt, 1e-8f));
        float alpha = -wt * ft + coshf(a) * dot;
        float dd = fabsf(asinhf(alpha / bet));
        float sg = (alpha > 0.f) ? 1.f : ((alpha < 0.f) ? -1.f : 0.f);
        out[b] = sg * bet * dd;
    }
}

// ------------------- launch -------------------
extern "C" void kernel_launch(void* const* d_in, const int* in_sizes, int n_in,
                              void* d_out, int out_size) {
    const float* x       = (const float*)d_in[0];
    const int*   domains = (const int*)  d_in[1];
    const float* conv1_w = (const float*)d_in[2];
    const float* bn1_w   = (const float*)d_in[3];
    const float* dw_w    = (const float*)d_in[5];
    const float* bn2_w   = (const float*)d_in[6];
    const float* bn2_b   = (const float*)d_in[7];
    const float* ec1_w   = (const float*)d_in[8];
    const float* b2c1_w  = (const float*)d_in[9];
    const float* b2c2_w  = (const float*)d_in[10];
    const float* bn3_w   = (const float*)d_in[11];
    const float* bn3_b   = (const float*)d_in[12];
    const float* lc1_w   = (const float*)d_in[13];
    const float* bn_beta = (const float*)d_in[14];
    const float* bn_gamma= (const float*)d_in[15];
    const float* mlr_a   = (const float*)d_in[16];
    const float* mlr_z   = (const float*)d_in[17];
    float* out = (float*)d_out;

    static int attr_set = 0;
    static cudaStream_t s1 = nullptr;
    static cudaEvent_t ev0 = nullptr, ev1 = nullptr;
    const int SMEMT = 45824 * 4;
    if (!attr_set) {
        cudaFuncSetAttribute(ktail, cudaFuncAttributeMaxDynamicSharedMemorySize, SMEMT);
        cudaStreamCreateWithFlags(&s1, cudaStreamNonBlocking);
        cudaEventCreateWithFlags(&ev0, cudaEventDisableTiming);
        cudaEventCreateWithFlags(&ev1, cudaEventDisableTiming);
        attr_set = 1;
    }

    k0_zero<<<1, 256>>>();
    cudaEventRecord(ev0, 0);
    cudaStreamWaitEvent(s1, ev0, 0);
    k1_stats<<<296, 256, 0, s1>>>(x);
    k2_bn1<<<1, 256, 0, s1>>>(conv1_w, bn1_w);
    cudaEventRecord(ev1, s1);
    // ktail launched WITHOUT waiting on ev1 — phase 0 runs concurrently with k1/k2,
    // phase A waits on the device-side g_a1flag set by k2.
    ktail<<<128, 512, SMEMT>>>(x, dw_w, conv1_w,
                               ec1_w, b2c1_w, b2c2_w, bn2_w, bn2_b,
                               bn3_w, bn3_b, lc1_w, domains,
                               bn_beta, bn_gamma, mlr_a, mlr_z, out);
    cudaStreamWaitEvent(0, ev1, 0);   // join side branch into the captured graph
}

// round 13
// speedup vs baseline: 1.1065x; 1.1065x over previous
#include <cuda_runtime.h>
#include <cuda_bf16.h>
#include <math.h>

#define BATCH 128
#define QSTRIDE 1028
#define WB 258
#define CC 33
#define NDOM 4
#define NTOT1 4198400.0
#define NTOT2 131200.0
#define NTOT3 33024.0

// ------------------- scratch -------------------
__device__ double gL[32];
__device__ double gHP[480];
__device__ double gTP[480];
__device__ double gHS[16];
__device__ double gTS[16];
__device__ double gSsum[1];
__device__ float  g_a1[16];
__device__ double g_qs[32], g_qq[32];
__device__ double g_bn3s[32], g_bn3q[32];
__device__ float  g_sdom[NDOM*CC];
__device__ float  g_cnt[NDOM];
__device__ float  g_dist2[NDOM];
__device__ float  g_q[BATCH*32*QSTRIDE];
__device__ volatile unsigned g_bar;

// ------------------- grid barrier (all 128 blocks co-resident) -------------------
__device__ __forceinline__ void grid_barrier(unsigned target) {
    __syncthreads();
    if (threadIdx.x == 0) {
        __threadfence();
        atomicAdd((unsigned*)&g_bar, 1u);
        while (g_bar < target) { }
        __threadfence();
    }
    __syncthreads();
}

// ------------------- K0: zero accumulators -------------------
__global__ void k0_zero() {
    int t = threadIdx.x;
    for (int i = t; i < 32; i += 256) gL[i] = 0.0;
    for (int i = t; i < 480; i += 256) { gHP[i] = 0.0; gTP[i] = 0.0; }
    for (int i = t; i < 16; i += 256) { gHS[i] = 0.0; gTS[i] = 0.0; }
    if (t == 0) { gSsum[0] = 0.0; g_bar = 0u; }
    for (int i = t; i < 32; i += 256) { g_qs[i]=0.0; g_qq[i]=0.0; g_bn3s[i]=0.0; g_bn3q[i]=0.0; }
    for (int i = t; i < NDOM*CC; i += 256) g_sdom[i] = 0.f;
    if (t < NDOM) { g_cnt[t] = 0.f; g_dist2[t] = 0.f; }
}

// ------------------- K1: conv1 stats via lag sums -------------------
__global__ void __launch_bounds__(256) k1_stats(const float* __restrict__ x) {
    __shared__ float xs[1056];
    int tid = threadIdx.x, lane = tid & 31, wrp = tid >> 5;
    int half = wrp & 1;
    int lg   = wrp >> 1;
    int dbase = 8 * lg;
    float accD[8];
#pragma unroll
    for (int d = 0; d < 8; d++) accD[d] = 0.f;
    float accS = 0.f;
    float accHP0=0.f, accHP1=0.f, accTP0=0.f, accTP1=0.f, accHS=0.f, accTS=0.f;

    for (int row = blockIdx.x; row < 4096; row += gridDim.x) {
        const float4* xr4 = (const float4*)(x + row * 1024);
        float4* xs4 = (float4*)xs;
        for (int i = tid; i < 264; i += 256)
            xs4[i] = (i < 256) ? xr4[i] : make_float4(0.f, 0.f, 0.f, 0.f);
        __syncthreads();
#pragma unroll
        for (int i = 0; i < 4; i++) {
            int t = 4*lane + 128*i + 512*half;
            float4 A  = *(const float4*)(xs + t);
            float4 W0 = *(const float4*)(xs + t + dbase);
            float4 W1 = *(const float4*)(xs + t + dbase + 4);
            float4 W2 = *(const float4*)(xs + t + dbase + 8);
            float a[4]  = {A.x, A.y, A.z, A.w};
            float w[12] = {W0.x,W0.y,W0.z,W0.w, W1.x,W1.y,W1.z,W1.w, W2.x,W2.y,W2.z,W2.w};
            if (lg == 0) accS += a[0] + a[1] + a[2] + a[3];
#pragma unroll
            for (int dl = 0; dl < 8; dl++)
#pragma unroll
                for (int p = 0; p < 4; p++)
                    accD[dl] = fmaf(a[p], w[p + dl], accD[dl]);
        }
        {
            int d = tid / 15, tt = tid % 15;
            accHP0 += xs[tt] * xs[tt + d];
            accTP0 += xs[1023 - d - tt] * xs[1023 - tt];
            if (tid < 224) {
                int idx = tid + 256;
                int d2 = idx / 15, t2 = idx % 15;
                accHP1 += xs[t2] * xs[t2 + d2];
                accTP1 += xs[1023 - d2 - t2] * xs[1023 - t2];
            }
        }
        if (tid < 16) { accHS += xs[tid]; accTS += xs[1023 - tid]; }
        __syncthreads();
    }
#pragma unroll
    for (int dl = 0; dl < 8; dl++) {
        float v = accD[dl];
        for (int o = 16; o > 0; o >>= 1) v += __shfl_down_sync(0xffffffffu, v, o);
        if (lane == 0) atomicAdd(&gL[dbase + dl], (double)v);
    }
    if (lg == 0) {
        float v = accS;
        for (int o = 16; o > 0; o >>= 1) v += __shfl_down_sync(0xffffffffu, v, o);
        if (lane == 0) atomicAdd(&gSsum[0], (double)v);
    }
    atomicAdd(&gHP[tid], (double)accHP0);
    atomicAdd(&gTP[tid], (double)accTP0);
    if (tid < 224) {
        atomicAdd(&gHP[tid + 256], (double)accHP1);
        atomicAdd(&gTP[tid + 256], (double)accTP1);
    }
    if (tid < 16) { atomicAdd(&gHS[tid], (double)accHS); atomicAdd(&gTS[tid], (double)accTS); }
}

// ------------------- K2: bn1 scale a1 -------------------
__global__ void __launch_bounds__(256) k2_bn1(const float* __restrict__ cw,
                                              const float* __restrict__ bn1w) {
    __shared__ double Tsh[32];
    __shared__ double Msh[1024];
    __shared__ double part[256];
    __shared__ double msh[16];
    int tid = threadIdx.x;
    if (tid < 32) {
        int k = tid;
        double v = gSsum[0];
        if (k <= 14) { for (int i = 0; i <= 14 - k; i++) v -= gTS[i]; }
        if (k >= 17) { for (int t = 0; t <= k - 17; t++) v -= gHS[t]; }
        Tsh[k] = v;
    }
    for (int idx = tid; idx < 1024; idx += 256) {
        int k = idx >> 5, k2 = idx & 31;
        int kl = min(k, k2), d = abs(k2 - k);
        double v = gL[d];
        if (kl >= 17) { for (int t = 0; t <= kl - 17; t++) v -= gHP[d * 15 + t]; }
        if (kl <= 14 - d) { for (int i = 0; i <= 14 - d - kl; i++) v -= gTP[d * 15 + i]; }
        Msh[idx] = v;
    }
    __syncthreads();
    if (tid < 16) {
        double m = 0.0;
        for (int k = 0; k < 32; k++) m += (double)cw[tid * 32 + k] * Tsh[k];
        msh[tid] = m / NTOT1;
    }
    {
        int o = tid >> 4, g = tid & 15;
        double p = 0.0;
#pragma unroll
        for (int kk = 2*g; kk < 2*g + 2; kk++) {
            double ck = (double)cw[o * 32 + kk];
            double inner = 0.0;
            for (int k2 = 0; k2 < 32; k2++)
                inner += (double)cw[o * 32 + k2] * Msh[kk * 32 + k2];
            p += ck * inner;
        }
        part[tid] = p;
    }
    __syncthreads();
    if (tid < 16) {
        double e2 = 0.0;
        for (int g2 = 0; g2 < 16; g2++) e2 += part[tid * 16 + g2];
        e2 /= NTOT1;
        double m = msh[tid];
        double var = e2 - m * m;
        g_a1[tid] = (float)((double)bn1w[tid] / sqrt(var + 1e-3));
    }
}

// ------------------- K34: fused z + conv1d + stats, 4 chunks of 256 -------------------
__global__ void __launch_bounds__(256) k34(const float* __restrict__ x,
                                           const float* __restrict__ dw,
                                           const float* __restrict__ cw) {
    extern __shared__ float sm[];
    float* zsh  = sm;            // 32*292 = 9344
    float* dwsh = sm + 9344;     // 1024
    float* cwsh = sm + 10368;    // 512
    float* sred = sm + 10880;    // 32
    float* qred = sm + 10912;    // 32
    int tid = threadIdx.x;
    int c = blockIdx.x, b = blockIdx.y;
    int base = c*256 - 16;
    const float* xb = x + b*32768;
    for (int i = tid; i < 1024; i += 256) dwsh[i] = dw[i];
    for (int i = tid; i < 512; i += 256) cwsh[i] = cw[i];
    if (tid < 32) { sred[tid] = 0.f; qred[tid] = 0.f; }
    __syncthreads();
    int wrp = tid >> 5, lane = tid & 31;
    int og = (wrp & 3) * 8;
    int th = wrp >> 2;
    float acc[5][8];
#pragma unroll
    for (int j = 0; j < 5; j++)
#pragma unroll
        for (int q = 0; q < 8; q++) acc[j][q] = 0.f;
    for (int h = 0; h < 32; h++) {
        float dwreg[8];
#pragma unroll
        for (int q = 0; q < 8; q++) dwreg[q] = dwsh[(og + q)*32 + h];
        const float* xh = xb + h*1024;
#pragma unroll
        for (int j = 0; j < 5; j++) {
            int tl = lane + 32*th + 64*j;
            int t = base + tl;
            float xv = (tl < 288 && (unsigned)t < 1024u) ? xh[t] : 0.f;
#pragma unroll
            for (int q = 0; q < 8; q++) acc[j][q] = fmaf(dwreg[q], xv, acc[j][q]);
        }
    }
#pragma unroll
    for (int j = 0; j < 5; j++) {
        int tl = lane + 32*th + 64*j;
        if (tl < 288)
#pragma unroll
            for (int q = 0; q < 8; q++) zsh[(og+q)*292 + tl] = acc[j][q];
    }
    __syncthreads();
    for (int r = 0; r < 4; r++) {
        int o2 = wrp + 8*r;
        float cwreg[32];
#pragma unroll
        for (int k = 0; k < 32; k++) cwreg[k] = cwsh[(o2 >> 1)*32 + k];
        const float* zrow = zsh + o2*292;
        float* qrow = g_q + (b*32 + o2)*QSTRIDE + c*256;
        float ps = 0.f, pq = 0.f;
#pragma unroll
        for (int m = 0; m < 2; m++) {
            int wl4 = 4*lane + 128*m;
            float wbuf[8];
            float4 v0 = *(const float4*)(zrow + wl4);
            float4 v1 = *(const float4*)(zrow + wl4 + 4);
            wbuf[0]=v0.x; wbuf[1]=v0.y; wbuf[2]=v0.z; wbuf[3]=v0.w;
            wbuf[4]=v1.x; wbuf[5]=v1.y; wbuf[6]=v1.z; wbuf[7]=v1.w;
            float a0=0.f, a1v=0.f, a2v=0.f, a3v=0.f;
#pragma unroll
            for (int k4 = 0; k4 < 8; k4++) {
#pragma unroll
                for (int kk = 0; kk < 4; kk++) {
                    float cv = cwreg[4*k4 + kk];
                    a0  = fmaf(cv, wbuf[kk],   a0);
                    a1v = fmaf(cv, wbuf[kk+1], a1v);
                    a2v = fmaf(cv, wbuf[kk+2], a2v);
                    a3v = fmaf(cv, wbuf[kk+3], a3v);
                }
                if (k4 < 7) {
                    float4 nv = *(const float4*)(zrow + wl4 + 4*k4 + 8);
                    wbuf[0]=wbuf[4]; wbuf[1]=wbuf[5]; wbuf[2]=wbuf[6]; wbuf[3]=wbuf[7];
                    wbuf[4]=nv.x; wbuf[5]=nv.y; wbuf[6]=nv.z; wbuf[7]=nv.w;
                }
            }
            *(float4*)(qrow + wl4) = make_float4(a0, a1v, a2v, a3v);
            ps += a0 + a1v + a2v + a3v;
            pq += a0*a0 + a1v*a1v + a2v*a2v + a3v*a3v;
        }
        for (int o = 16; o > 0; o >>= 1) {
            ps += __shfl_down_sync(0xffffffffu, ps, o);
            pq += __shfl_down_sync(0xffffffffu, pq, o);
        }
        if (lane == 0) { atomicAdd(&sred[o2], ps); atomicAdd(&qred[o2], pq); }
    }
    if (c == 3 && tid < 32) {
        int o2 = tid;
        float y = 0.f;
        for (int k = 0; k < 32; k++) y += cwsh[(o2>>1)*32 + k] * zsh[o2*292 + 256 + k];
        g_q[(b*32 + o2)*QSTRIDE + 1024] = y;
        atomicAdd(&sred[o2], y); atomicAdd(&qred[o2], y*y);
    }
    __syncthreads();
    if (tid < 32) {
        atomicAdd(&g_qs[tid], (double)sred[tid]);
        atomicAdd(&g_qq[tid], (double)qred[tid]);
    }
}

// ------------------- KTAIL: k6 + k7 + k9 + k10 fused (grid=128, 1024 thr, grid barriers) ----
__global__ void __launch_bounds__(1024) ktail(const float* __restrict__ e1,
                                             const float* __restrict__ e2w,
                                             const float* __restrict__ pw,
                                             const float* __restrict__ bn2w,
                                             const float* __restrict__ bn2b,
                                             const float* __restrict__ bn3w,
                                             const float* __restrict__ bn3b,
                                             const float* __restrict__ lc1,
                                             const int* __restrict__ domains,
                                             const float* __restrict__ beta,
                                             const float* __restrict__ gamma,
                                             const float* __restrict__ mlra,
                                             const float* __restrict__ z,
                                             float* __restrict__ out) {
    extern __shared__ float sm[];
    float* ps  = sm;          // 32*272 (data at +8) -- dead after conv1
    float* q1  = sm + 8704;   // 32*280 (data at +8) -- dead after conv2
    float* q2  = sm + 17664;  // 32*260 -- dead after pointwise
    float* we1 = sm + 25984;  // 512
    float* we2 = sm + 26496;  // 512
    float* wpp = sm + 27008;  // 1024
    float* rr  = sm;          // 32*260 = 8320 (overlays dead ps)
    float* lcw = sm + 8704;   // 1089
    float* sp  = sm + 9800;   // 64*33 = 2112 (pts)
    float* vv  = sm + 12000;  // 64*33 = 2112 (s buffer, then v)
    float* hsm = sm + 14200;  // 64*33 = 2112
    float* pl  = sm + 16400;  // 16*33 = 528
    __shared__ float s2sh[32], h2sh[32];
    __shared__ float a3[32], c3[32];
    __shared__ float mus[33], bs[33];
    __shared__ float dnv;
    __shared__ float redA[64], redB[64], redC[64];
    int tid = threadIdx.x, b = blockIdx.x;
    int dom = domains[b];

    // ================= Phase A: bn2-affine + elu + pool + ec1 + b2c1 + b2c2 + bn3 stats ======
    for (int i = tid; i < 25984; i += 1024) sm[i] = 0.f;
    if (tid < 512) { we1[tid] = e1[tid]; we2[tid] = e2w[tid]; }
    else if (tid >= 512) { int j = tid - 512; if (j < 512) { } }
    for (int i = tid; i < 1024; i += 1024) wpp[i] = pw[i];
    if (tid < 32) {
        double mq = g_qs[tid] / NTOT2;
        double vq = g_qq[tid] / NTOT2 - mq*mq;
        double a1 = (double)g_a1[tid >> 1];
        double sc = a1 * (double)bn2w[tid] / sqrt(a1*a1*vq + 1e-3);
        s2sh[tid] = (float)sc;
        h2sh[tid] = (float)((double)bn2b[tid] - mq*sc);
    }
    __syncthreads();
    for (int i = tid; i < 8192; i += 1024) {
        int o = i >> 8, w = i & 255;
        float sc = s2sh[o], sh = h2sh[o];
        float4 v = *(const float4*)(g_q + (size_t)(b*32 + o)*QSTRIDE + 4*w);
        float vl[4] = {v.x, v.y, v.z, v.w};
        float s = 0.f;
#pragma unroll
        for (int j = 0; j < 4; j++) {
            float y = fmaf(sc, vl[j], sh);
            s += (y > 0.f) ? y : expm1f(y);
        }
        ps[o*272 + 8 + w] = s * 0.25f;
    }
    __syncthreads();
    // conv1: w in [0,257)
    for (int g = tid; g < 2080; g += 1024) {
        int o = g / 65, w4 = (g - o*65) * 4;
        const float* prow = ps + o*272 + w4;
        float wbuf[8];
        float4 v0 = *(const float4*)(prow);
        float4 v1 = *(const float4*)(prow + 4);
        wbuf[0]=v0.x; wbuf[1]=v0.y; wbuf[2]=v0.z; wbuf[3]=v0.w;
        wbuf[4]=v1.x; wbuf[5]=v1.y; wbuf[6]=v1.z; wbuf[7]=v1.w;
        float a0=0.f,a1=0.f,a2=0.f,a3v=0.f;
#pragma unroll
        for (int k4 = 0; k4 < 4; k4++) {
#pragma unroll
            for (int kk = 0; kk < 4; kk++) {
                float wv = we1[o*16 + 4*k4 + kk];
                a0  = fmaf(wv, wbuf[kk],   a0);
                a1  = fmaf(wv, wbuf[kk+1], a1);
                a2  = fmaf(wv, wbuf[kk+2], a2);
                a3v = fmaf(wv, wbuf[kk+3], a3v);
            }
            if (k4 < 3) {
                float4 nv = *(const float4*)(prow + 8 + 4*k4);
                wbuf[0]=wbuf[4]; wbuf[1]=wbuf[5]; wbuf[2]=wbuf[6]; wbuf[3]=wbuf[7];
                wbuf[4]=nv.x; wbuf[5]=nv.y; wbuf[6]=nv.z; wbuf[7]=nv.w;
            }
        }
        float* q1r = q1 + o*280 + 8 + w4;
        if (w4     < 257) q1r[0] = a0;
        if (w4 + 1 < 257) q1r[1] = a1;
        if (w4 + 2 < 257) q1r[2] = a2;
        if (w4 + 3 < 257) q1r[3] = a3v;
    }
    __syncthreads();
    // conv2: w in [0,258)
    for (int g = tid; g < 2080; g += 1024) {
        int o = g / 65, w4 = (g - o*65) * 4;
        const float* prow = q1 + o*280 + w4;
        float wbuf[8];
        float4 v0 = *(const float4*)(prow);
        float4 v1 = *(const float4*)(prow + 4);
        wbuf[0]=v0.x; wbuf[1]=v0.y; wbuf[2]=v0.z; wbuf[3]=v0.w;
        wbuf[4]=v1.x; wbuf[5]=v1.y; wbuf[6]=v1.z; wbuf[7]=v1.w;
        float a0=0.f,a1=0.f,a2=0.f,a3v=0.f;
#pragma unroll
        for (int k4 = 0; k4 < 4; k4++) {
#pragma unroll
            for (int kk = 0; kk < 4; kk++) {
                float wv = we2[o*16 + 4*k4 + kk];
                a0  = fmaf(wv, wbuf[kk],   a0);
                a1  = fmaf(wv, wbuf[kk+1], a1);
                a2  = fmaf(wv, wbuf[kk+2], a2);
                a3v = fmaf(wv, wbuf[kk+3], a3v);
            }
            if (k4 < 3) {
                float4 nv = *(const float4*)(prow + 8 + 4*k4);
                wbuf[0]=wbuf[4]; wbuf[1]=wbuf[5]; wbuf[2]=wbuf[6]; wbuf[3]=wbuf[7];
                wbuf[4]=nv.x; wbuf[5]=nv.y; wbuf[6]=nv.z; wbuf[7]=nv.w;
            }
        }
        float* q2r = q2 + o*260 + w4;
        if (w4     < 258) q2r[0] = a0;
        if (w4 + 1 < 258) q2r[1] = a1;
        if (w4 + 2 < 258) q2r[2] = a2;
        if (w4 + 3 < 258) q2r[3] = a3v;
    }
    __syncthreads();
    // pointwise 32x32: one channel per warp (1024 threads = 32 warps)
    {
        int o = tid >> 5;          // warp id = channel
        int wslot = tid & 31;
        float ls = 0.f, lq = 0.f;
        for (int it = 0; it < 3; it++) {
            int w4 = 4*(wslot + 32*it);
            if (w4 > 256) continue;
            float a0=0.f,a1=0.f,a2=0.f,a3v=0.f;
#pragma unroll 8
            for (int c = 0; c < 32; c++) {
                float4 qv = *(const float4*)(q2 + c*260 + w4);
                float wv = wpp[o*32 + c];
                a0  = fmaf(wv, qv.x, a0);
                a1  = fmaf(wv, qv.y, a1);
                a2  = fmaf(wv, qv.z, a2);
                a3v = fmaf(wv, qv.w, a3v);
            }
            float* r0 = rr + o*260 + w4;
            int nv = WB - w4;
            if (nv > 0) { r0[0]=a0;  ls+=a0;  lq+=a0*a0; }
            if (nv > 1) { r0[1]=a1;  ls+=a1;  lq+=a1*a1; }
            if (nv > 2) { r0[2]=a2;  ls+=a2;  lq+=a2*a2; }
            if (nv > 3) { r0[3]=a3v; ls+=a3v; lq+=a3v*a3v; }
        }
        for (int d = 16; d > 0; d >>= 1) {
            ls += __shfl_down_sync(0xffffffffu, ls, d);
            lq += __shfl_down_sync(0xffffffffu, lq, d);
        }
        if (wslot == 0) {
            atomicAdd(&g_bn3s[o], (double)ls);
            atomicAdd(&g_bn3q[o], (double)lq);
        }
    }
    grid_barrier(128u);

    // ================= Phase B: bn3+elu+pool+normalize+lift -> pts (sp), domain sums =========
    for (int i = tid; i < 1089; i += 1024) lcw[i] = lc1[i];
    if (tid < 32) {
        double mean = g_bn3s[tid] / NTOT3;
        double var = g_bn3q[tid] / NTOT3 - mean * mean;
        float a = (float)((double)bn3w[tid] / sqrt(var + 1e-3));
        a3[tid] = a;
        c3[tid] = (float)((double)bn3b[tid] - mean * (double)a);
    }
    __syncthreads();
    for (int t = tid; t < 2048; t += 1024) {
        int w = t >> 5, c = t & 31;
        const float* rb = rr + c * 260 + w * 4;
        float acc = 0.f;
#pragma unroll
        for (int i = 0; i < 4; i++) {
            float v = a3[c] * rb[i] + c3[c];
            acc += (v > 0.f) ? v : expm1f(v);
        }
        vv[w * 33 + c] = acc * 0.25f;
    }
    __syncthreads();
    if (tid < 64) {
        int w = tid;
        float ssq = 0.f;
        for (int c = 0; c < 32; c++) { float sv = vv[w*33+c]; ssq += sv * sv; }
        float inv = 1.f / fmaxf(sqrtf(ssq), 1e-12f);
        float hs2 = 0.f;
        for (int c = 0; c < 32; c++) { float sv = vv[w*33+c] * inv; vv[w*33+c] = sv; hs2 += sv * sv; }
        vv[w * 33 + 32] = sqrtf(1.f + hs2);
    }
    __syncthreads();
    for (int t = tid; t < 2048; t += 1024) {
        int w = t >> 5, o = (t & 31) + 1;
        float acc = lcw[o * 33] * vv[w * 33 + 32];
#pragma unroll
        for (int c = 0; c < 32; c++) acc = fmaf(lcw[o * 33 + 1 + c], vv[w * 33 + c], acc);
        sp[w * 33 + o] = acc;
    }
    __syncthreads();
    if (tid < 64) {
        float ysq = 0.f;
        for (int o = 1; o < 33; o++) { float pv = sp[tid*33+o]; ysq += pv * pv; }
        sp[tid * 33] = sqrtf(1.f + ysq);
    }
    __syncthreads();
    if (tid < 33) {
        float acc = 0.f;
        for (int ww = 0; ww < 64; ww++) acc += sp[ww * 33 + tid];
        atomicAdd(&g_sdom[dom * 33 + tid], acc);
    }
    if (tid == 0) atomicAdd(&g_cnt[dom], 64.f);
    grid_barrier(256u);

    // ================= Phase C: mu + log-map + transport, dist^2 =============================
    if (tid < 33) {
        float cnt = fmaxf(g_cnt[dom], 1.f);
        mus[tid] = g_sdom[dom * 33 + tid] / cnt;
    }
    __syncthreads();
    if (tid == 0) {
        float mm = -mus[0] * mus[0];
        for (int j = 1; j < 33; j++) mm += mus[j] * mus[j];
        dnv = sqrtf(fmaxf(fabsf(mm), 1e-8f));
    }
    __syncthreads();
    if (tid < 33) mus[tid] = mus[tid] / dnv;
    __syncthreads();
    if (tid < 64) {
        float p[33];
        for (int j = 0; j < 33; j++) p[j] = sp[tid * 33 + j];
        float ip = -mus[0] * p[0];
        for (int j = 1; j < 33; j++) ip += mus[j] * p[j];
        float ci = fmaxf(-ip, 1.f + 1e-7f);
        float dist = acoshf(ci);
        float u[33];
        for (int j = 0; j < 33; j++) u[j] = p[j] + ip * mus[j];
        float muu = -u[0] * u[0];
        for (int j = 1; j < 33; j++) muu += u[j] * u[j];
        float un = sqrtf(fmaxf(muu, 1e-8f));
        float sc = dist / un;
        float v0 = sc * u[0];
        float f = -v0 / (1.f + mus[0]);
        vv[tid * 33 + 0] = v0 + f * (mus[0] + 1.f);
        for (int j = 1; j < 33; j++) vv[tid * 33 + j] = sc * u[j] + f * mus[j];
        redA[tid] = dist * dist;
    }
    __syncthreads();
    if (tid == 0) {
        float s = 0.f;
        for (int i = 0; i < 64; i++) s += redA[i];
        atomicAdd(&g_dist2[dom], s);
    }
    grid_barrier(384u);

    // ================= Phase D: scale + beta transport + exp-map + elu + pool + out ==========
    if (tid < 33) bs[tid] = beta[tid];
    __syncthreads();
    if (tid < 64) {
        float cnt = fmaxf(g_cnt[dom], 1.f);
        float var = g_dist2[dom] / cnt;
        float scale = gamma[0] / sqrtf(var + 1e-5f);
        float v[33];
        for (int j = 0; j < 33; j++) v[j] = vv[tid * 33 + j] * scale;
        float mb = -bs[0] * v[0];
        for (int j = 1; j < 33; j++) mb += bs[j] * v[j];
        float f = mb / (1.f + bs[0]);
        v[0] += f * (1.f + bs[0]);
        for (int j = 1; j < 33; j++) v[j] += f * bs[j];
        float mv = -v[0] * v[0];
        for (int j = 1; j < 33; j++) mv += v[j] * v[j];
        float vn = sqrtf(fmaxf(mv, 1e-8f));
        float ch = coshf(vn), sh = sinhf(vn) / vn;
        float ssum = 0.f;
        float sv[33];
        for (int j = 1; j < 33; j++) {
            float y = ch * bs[j] + sh * v[j];
            float e = (y > 0.f) ? y : expm1f(y);
            sv[j] = e;
            ssum += e * e;
        }
        hsm[tid * 33 + 0] = sqrtf(1.f + ssum);
        for (int j = 1; j < 33; j++) hsm[tid * 33 + j] = sv[j];
    }
    __syncthreads();
    if (tid < 16) {
        float m[33];
        for (int j = 0; j < 33; j++) {
            m[j] = 0.25f * (hsm[(4 * tid) * 33 + j] + hsm[(4 * tid + 1) * 33 + j] +
                            hsm[(4 * tid + 2) * 33 + j] + hsm[(4 * tid + 3) * 33 + j]);
        }
        float mm = -m[0] * m[0];
        for (int j = 1; j < 33; j++) mm += m[j] * m[j];
        float dnm = sqrtf(fmaxf(fabsf(mm), 1e-8f));
        for (int j = 0; j < 33; j++) pl[tid * 33 + j] = m[j] / dnm;
    }
    __syncthreads();
    if (tid < 64) {
        float pssq = 0.f, pdot = 0.f, pz2 = 0.f;
        for (int i = tid; i < 512; i += 64) {
            int g = i >> 5, j = (i & 31) + 1;
            float fv = pl[g * 33 + j];
            out[128 + b * 513 + 1 + i] = fv;
            float zv = z[i];
            pssq += fv * fv;
            pdot += fv * zv;
            pz2  += zv * zv;
        }
        redA[tid] = pssq;
        redB[tid] = pdot;
        redC[tid] = pz2;
    }
    __syncthreads();
    if (tid == 0) {
        float ssq = 0.f, dot = 0.f, z2 = 0.f;
        for (int i = 0; i < 64; i++) { ssq += redA[i]; dot += redB[i]; z2 += redC[i]; }
        float ft = sqrtf(1.f + ssq);
        out[128 + b * 513] = ft;
        float a = mlra[0], nz = sqrtf(z2);
        float wt = sinhf(a) * nz;
        float cz = coshf(a) * nz;
        float bet = sqrtf(fmaxf(cz * cz - wt * wt, 1e-8f));
        float alpha = -wt * ft + coshf(a) * dot;
        float dd = fabsf(asinhf(alpha / bet));
        float sg = (alpha > 0.f) ? 1.f : ((alpha < 0.f) ? -1.f : 0.f);
        out[b] = sg * bet * dd;
    }
}

// ------------------- launch -------------------
extern "C" void kernel_launch(void* const* d_in, const int* in_sizes, int n_in,
                              void* d_out, int out_size) {
    const float* x       = (const float*)d_in[0];
    const int*   domains = (const int*)  d_in[1];
    const float* conv1_w = (const float*)d_in[2];
    const float* bn1_w   = (const float*)d_in[3];
    const float* dw_w    = (const float*)d_in[5];
    const float* bn2_w   = (const float*)d_in[6];
    const float* bn2_b   = (const float*)d_in[7];
    const float* ec1_w   = (const float*)d_in[8];
    const float* b2c1_w  = (const float*)d_in[9];
    const float* b2c2_w  = (const float*)d_in[10];
    const float* bn3_w   = (const float*)d_in[11];
    const float* bn3_b   = (const float*)d_in[12];
    const float* lc1_w   = (const float*)d_in[13];
    const float* bn_beta = (const float*)d_in[14];
    const float* bn_gamma= (const float*)d_in[15];
    const float* mlr_a   = (const float*)d_in[16];
    const float* mlr_z   = (const float*)d_in[17];
    float* out = (float*)d_out;

    static int attr_set = 0;
    static cudaStream_t s1 = nullptr;
    static cudaEvent_t ev0 = nullptr, ev1 = nullptr;
    const int SMEM34 = 10944 * 4;
    const int SMEMT  = 28032 * 4;
    if (!attr_set) {
        cudaFuncSetAttribute(k34,   cudaFuncAttributeMaxDynamicSharedMemorySize, SMEM34);
        cudaFuncSetAttribute(ktail, cudaFuncAttributeMaxDynamicSharedMemorySize, SMEMT);
        cudaStreamCreateWithFlags(&s1, cudaStreamNonBlocking);
        cudaEventCreateWithFlags(&ev0, cudaEventDisableTiming);
        cudaEventCreateWithFlags(&ev1, cudaEventDisableTiming);
        attr_set = 1;
    }

    k0_zero<<<1, 256>>>();
    cudaEventRecord(ev0, 0);
    cudaStreamWaitEvent(s1, ev0, 0);
    k1_stats<<<296, 256, 0, s1>>>(x);
    k2_bn1<<<1, 256, 0, s1>>>(conv1_w, bn1_w);
    cudaEventRecord(ev1, s1);
    k34<<<dim3(4, 128), 256, SMEM34>>>(x, dw_w, conv1_w);
    cudaStreamWaitEvent(0, ev1, 0);
    ktail<<<128, 1024, SMEMT>>>(ec1_w, b2c1_w, b2c2_w, bn2_w, bn2_b,
                                bn3_w, bn3_b, lc1_w, domains,
                                bn_beta, bn_gamma, mlr_a, mlr_z, out);
}

// round 14
// speedup vs baseline: 1.1128x; 1.0057x over previous
#include <cuda_runtime.h>
#include <cuda_bf16.h>
#include <math.h>

#define BATCH 128
#define QSTRIDE 1028
#define WB 258
#define CC 33
#define NDOM 4
#define NTOT1 4198400.0
#define NTOT2 131200.0
#define NTOT3 33024.0

// ------------------- scratch -------------------
__device__ double gL[32];
__device__ double gHP[480];
__device__ double gTP[480];
__device__ double gHS[16];
__device__ double gTS[16];
__device__ double gSsum[1];
__device__ float  g_a1[16];
__device__ double g_qs[32], g_qq[32];
__device__ double g_bn3s[32], g_bn3q[32];
__device__ float  g_sdom[NDOM*CC];
__device__ float  g_cnt[NDOM];
__device__ float  g_dist2[NDOM];
__device__ float  g_q[BATCH*32*QSTRIDE];
__device__ volatile unsigned g_bar;

// ------------------- grid barrier (all 128 blocks co-resident) -------------------
__device__ __forceinline__ void grid_barrier(unsigned target) {
    __syncthreads();
    if (threadIdx.x == 0) {
        __threadfence();
        atomicAdd((unsigned*)&g_bar, 1u);
        while (g_bar < target) { }
        __threadfence();
    }
    __syncthreads();
}

// ------------------- K0: zero accumulators -------------------
__global__ void k0_zero() {
    int t = threadIdx.x;
    for (int i = t; i < 32; i += 256) gL[i] = 0.0;
    for (int i = t; i < 480; i += 256) { gHP[i] = 0.0; gTP[i] = 0.0; }
    for (int i = t; i < 16; i += 256) { gHS[i] = 0.0; gTS[i] = 0.0; }
    if (t == 0) { gSsum[0] = 0.0; g_bar = 0u; }
    for (int i = t; i < 32; i += 256) { g_qs[i]=0.0; g_qq[i]=0.0; g_bn3s[i]=0.0; g_bn3q[i]=0.0; }
    for (int i = t; i < NDOM*CC; i += 256) g_sdom[i] = 0.f;
    if (t < NDOM) { g_cnt[t] = 0.f; g_dist2[t] = 0.f; }
}

// ------------------- K1: conv1 stats via lag sums -------------------
__global__ void __launch_bounds__(256) k1_stats(const float* __restrict__ x) {
    __shared__ float xs[1056];
    int tid = threadIdx.x, lane = tid & 31, wrp = tid >> 5;
    int half = wrp & 1;
    int lg   = wrp >> 1;
    int dbase = 8 * lg;
    float accD[8];
#pragma unroll
    for (int d = 0; d < 8; d++) accD[d] = 0.f;
    float accS = 0.f;
    float accHP0=0.f, accHP1=0.f, accTP0=0.f, accTP1=0.f, accHS=0.f, accTS=0.f;

    for (int row = blockIdx.x; row < 4096; row += gridDim.x) {
        const float4* xr4 = (const float4*)(x + row * 1024);
        float4* xs4 = (float4*)xs;
        for (int i = tid; i < 264; i += 256)
            xs4[i] = (i < 256) ? xr4[i] : make_float4(0.f, 0.f, 0.f, 0.f);
        __syncthreads();
#pragma unroll
        for (int i = 0; i < 4; i++) {
            int t = 4*lane + 128*i + 512*half;
            float4 A  = *(const float4*)(xs + t);
            float4 W0 = *(const float4*)(xs + t + dbase);
            float4 W1 = *(const float4*)(xs + t + dbase + 4);
            float4 W2 = *(const float4*)(xs + t + dbase + 8);
            float a[4]  = {A.x, A.y, A.z, A.w};
            float w[12] = {W0.x,W0.y,W0.z,W0.w, W1.x,W1.y,W1.z,W1.w, W2.x,W2.y,W2.z,W2.w};
            if (lg == 0) accS += a[0] + a[1] + a[2] + a[3];
#pragma unroll
            for (int dl = 0; dl < 8; dl++)
#pragma unroll
                for (int p = 0; p < 4; p++)
                    accD[dl] = fmaf(a[p], w[p + dl], accD[dl]);
        }
        {
            int d = tid / 15, tt = tid % 15;
            accHP0 += xs[tt] * xs[tt + d];
            accTP0 += xs[1023 - d - tt] * xs[1023 - tt];
            if (tid < 224) {
                int idx = tid + 256;
                int d2 = idx / 15, t2 = idx % 15;
                accHP1 += xs[t2] * xs[t2 + d2];
                accTP1 += xs[1023 - d2 - t2] * xs[1023 - t2];
            }
        }
        if (tid < 16) { accHS += xs[tid]; accTS += xs[1023 - tid]; }
        __syncthreads();
    }
#pragma unroll
    for (int dl = 0; dl < 8; dl++) {
        float v = accD[dl];
        for (int o = 16; o > 0; o >>= 1) v += __shfl_down_sync(0xffffffffu, v, o);
        if (lane == 0) atomicAdd(&gL[dbase + dl], (double)v);
    }
    if (lg == 0) {
        float v = accS;
        for (int o = 16; o > 0; o >>= 1) v += __shfl_down_sync(0xffffffffu, v, o);
        if (lane == 0) atomicAdd(&gSsum[0], (double)v);
    }
    atomicAdd(&gHP[tid], (double)accHP0);
    atomicAdd(&gTP[tid], (double)accTP0);
    if (tid < 224) {
        atomicAdd(&gHP[tid + 256], (double)accHP1);
        atomicAdd(&gTP[tid + 256], (double)accTP1);
    }
    if (tid < 16) { atomicAdd(&gHS[tid], (double)accHS); atomicAdd(&gTS[tid], (double)accTS); }
}

// ------------------- K2: bn1 scale a1 -------------------
__global__ void __launch_bounds__(256) k2_bn1(const float* __restrict__ cw,
                                              const float* __restrict__ bn1w) {
    __shared__ double Tsh[32];
    __shared__ double Msh[1024];
    __shared__ double part[256];
    __shared__ double msh[16];
    int tid = threadIdx.x;
    if (tid < 32) {
        int k = tid;
        double v = gSsum[0];
        if (k <= 14) { for (int i = 0; i <= 14 - k; i++) v -= gTS[i]; }
        if (k >= 17) { for (int t = 0; t <= k - 17; t++) v -= gHS[t]; }
        Tsh[k] = v;
    }
    for (int idx = tid; idx < 1024; idx += 256) {
        int k = idx >> 5, k2 = idx & 31;
        int kl = min(k, k2), d = abs(k2 - k);
        double v = gL[d];
        if (kl >= 17) { for (int t = 0; t <= kl - 17; t++) v -= gHP[d * 15 + t]; }
        if (kl <= 14 - d) { for (int i = 0; i <= 14 - d - kl; i++) v -= gTP[d * 15 + i]; }
        Msh[idx] = v;
    }
    __syncthreads();
    if (tid < 16) {
        double m = 0.0;
        for (int k = 0; k < 32; k++) m += (double)cw[tid * 32 + k] * Tsh[k];
        msh[tid] = m / NTOT1;
    }
    {
        int o = tid >> 4, g = tid & 15;
        double p = 0.0;
#pragma unroll
        for (int kk = 2*g; kk < 2*g + 2; kk++) {
            double ck = (double)cw[o * 32 + kk];
            double inner = 0.0;
            for (int k2 = 0; k2 < 32; k2++)
                inner += (double)cw[o * 32 + k2] * Msh[kk * 32 + k2];
            p += ck * inner;
        }
        part[tid] = p;
    }
    __syncthreads();
    if (tid < 16) {
        double e2 = 0.0;
        for (int g2 = 0; g2 < 16; g2++) e2 += part[tid * 16 + g2];
        e2 /= NTOT1;
        double m = msh[tid];
        double var = e2 - m * m;
        g_a1[tid] = (float)((double)bn1w[tid] / sqrt(var + 1e-3));
    }
}

// ------------------- K34: fused z + conv1d + stats, 4 chunks of 256 -------------------
__global__ void __launch_bounds__(256) k34(const float* __restrict__ x,
                                           const float* __restrict__ dw,
                                           const float* __restrict__ cw) {
    extern __shared__ float sm[];
    float* zsh  = sm;            // 32*292 = 9344
    float* dwsh = sm + 9344;     // 1024
    float* cwsh = sm + 10368;    // 512
    float* sred = sm + 10880;    // 32
    float* qred = sm + 10912;    // 32
    int tid = threadIdx.x;
    int c = blockIdx.x, b = blockIdx.y;
    int base = c*256 - 16;
    const float* xb = x + b*32768;
    for (int i = tid; i < 1024; i += 256) dwsh[i] = dw[i];
    for (int i = tid; i < 512; i += 256) cwsh[i] = cw[i];
    if (tid < 32) { sred[tid] = 0.f; qred[tid] = 0.f; }
    __syncthreads();
    int wrp = tid >> 5, lane = tid & 31;
    int og = (wrp & 3) * 8;
    int th = wrp >> 2;
    float acc[5][8];
#pragma unroll
    for (int j = 0; j < 5; j++)
#pragma unroll
        for (int q = 0; q < 8; q++) acc[j][q] = 0.f;
    for (int h = 0; h < 32; h++) {
        float dwreg[8];
#pragma unroll
        for (int q = 0; q < 8; q++) dwreg[q] = dwsh[(og + q)*32 + h];
        const float* xh = xb + h*1024;
#pragma unroll
        for (int j = 0; j < 5; j++) {
            int tl = lane + 32*th + 64*j;
            int t = base + tl;
            float xv = (tl < 288 && (unsigned)t < 1024u) ? xh[t] : 0.f;
#pragma unroll
            for (int q = 0; q < 8; q++) acc[j][q] = fmaf(dwreg[q], xv, acc[j][q]);
        }
    }
#pragma unroll
    for (int j = 0; j < 5; j++) {
        int tl = lane + 32*th + 64*j;
        if (tl < 288)
#pragma unroll
            for (int q = 0; q < 8; q++) zsh[(og+q)*292 + tl] = acc[j][q];
    }
    __syncthreads();
    for (int r = 0; r < 4; r++) {
        int o2 = wrp + 8*r;
        float cwreg[32];
#pragma unroll
        for (int k = 0; k < 32; k++) cwreg[k] = cwsh[(o2 >> 1)*32 + k];
        const float* zrow = zsh + o2*292;
        float* qrow = g_q + (b*32 + o2)*QSTRIDE + c*256;
        float ps = 0.f, pq = 0.f;
#pragma unroll
        for (int m = 0; m < 2; m++) {
            int wl4 = 4*lane + 128*m;
            float wbuf[8];
            float4 v0 = *(const float4*)(zrow + wl4);
            float4 v1 = *(const float4*)(zrow + wl4 + 4);
            wbuf[0]=v0.x; wbuf[1]=v0.y; wbuf[2]=v0.z; wbuf[3]=v0.w;
            wbuf[4]=v1.x; wbuf[5]=v1.y; wbuf[6]=v1.z; wbuf[7]=v1.w;
            float a0=0.f, a1v=0.f, a2v=0.f, a3v=0.f;
#pragma unroll
            for (int k4 = 0; k4 < 8; k4++) {
#pragma unroll
                for (int kk = 0; kk < 4; kk++) {
                    float cv = cwreg[4*k4 + kk];
                    a0  = fmaf(cv, wbuf[kk],   a0);
                    a1v = fmaf(cv, wbuf[kk+1], a1v);
                    a2v = fmaf(cv, wbuf[kk+2], a2v);
                    a3v = fmaf(cv, wbuf[kk+3], a3v);
                }
                if (k4 < 7) {
                    float4 nv = *(const float4*)(zrow + wl4 + 4*k4 + 8);
                    wbuf[0]=wbuf[4]; wbuf[1]=wbuf[5]; wbuf[2]=wbuf[6]; wbuf[3]=wbuf[7];
                    wbuf[4]=nv.x; wbuf[5]=nv.y; wbuf[6]=nv.z; wbuf[7]=nv.w;
                }
            }
            *(float4*)(qrow + wl4) = make_float4(a0, a1v, a2v, a3v);
            ps += a0 + a1v + a2v + a3v;
            pq += a0*a0 + a1v*a1v + a2v*a2v + a3v*a3v;
        }
        for (int o = 16; o > 0; o >>= 1) {
            ps += __shfl_down_sync(0xffffffffu, ps, o);
            pq += __shfl_down_sync(0xffffffffu, pq, o);
        }
        if (lane == 0) { atomicAdd(&sred[o2], ps); atomicAdd(&qred[o2], pq); }
    }
    if (c == 3 && tid < 32) {
        int o2 = tid;
        float y = 0.f;
        for (int k = 0; k < 32; k++) y += cwsh[(o2>>1)*32 + k] * zsh[o2*292 + 256 + k];
        g_q[(b*32 + o2)*QSTRIDE + 1024] = y;
        atomicAdd(&sred[o2], y); atomicAdd(&qred[o2], y*y);
    }
    __syncthreads();
    if (tid < 32) {
        atomicAdd(&g_qs[tid], (double)sred[tid]);
        atomicAdd(&g_qq[tid], (double)qred[tid]);
    }
}

// ------------------- KTAIL: k6 + k7 + k9 + k10 fused (grid=128, 1024 thr, grid barriers) ----
// Phases C/D are smem-resident: no 33-float register arrays (avoids spills at 64-reg cap).
__global__ void __launch_bounds__(1024) ktail(const float* __restrict__ e1,
                                             const float* __restrict__ e2w,
                                             const float* __restrict__ pw,
                                             const float* __restrict__ bn2w,
                                             const float* __restrict__ bn2b,
                                             const float* __restrict__ bn3w,
                                             const float* __restrict__ bn3b,
                                             const float* __restrict__ lc1,
                                             const int* __restrict__ domains,
                                             const float* __restrict__ beta,
                                             const float* __restrict__ gamma,
                                             const float* __restrict__ mlra,
                                             const float* __restrict__ z,
                                             float* __restrict__ out) {
    extern __shared__ float sm[];
    float* ps  = sm;          // 32*272 (data at +8) -- dead after conv1
    float* q1  = sm + 8704;   // 32*280 (data at +8) -- dead after conv2
    float* q2  = sm + 17664;  // 32*260 -- dead after pointwise
    float* we1 = sm + 25984;  // 512
    float* we2 = sm + 26496;  // 512
    float* wpp = sm + 27008;  // 1024
    float* rr  = sm;          // 32*260 = 8320 (overlays dead ps)
    float* lcw = sm + 8704;   // 1089
    float* sp  = sm + 9800;   // 64*33 = 2112 (pts)
    float* vv  = sm + 12000;  // 64*33 = 2112 (s buffer, then v)
    float* hsm = sm + 14200;  // 64*33 = 2112
    float* pl  = sm + 16400;  // 16*33 = 528
    __shared__ float s2sh[32], h2sh[32];
    __shared__ float a3[32], c3[32];
    __shared__ float mus[33], bs[33];
    __shared__ float dnv;
    __shared__ float redA[64], redB[64], redC[64];
    int tid = threadIdx.x, b = blockIdx.x;
    int dom = domains[b];

    // ================= Phase A: bn2-affine + elu + pool + ec1 + b2c1 + b2c2 + bn3 stats ======
    for (int i = tid; i < 25984; i += 1024) sm[i] = 0.f;
    if (tid < 512) { we1[tid] = e1[tid]; we2[tid] = e2w[tid]; }
    if (tid < 1024) wpp[tid] = pw[tid];
    if (tid < 32) {
        double mq = g_qs[tid] / NTOT2;
        double vq = g_qq[tid] / NTOT2 - mq*mq;
        double a1 = (double)g_a1[tid >> 1];
        double sc = a1 * (double)bn2w[tid] / sqrt(a1*a1*vq + 1e-3);
        s2sh[tid] = (float)sc;
        h2sh[tid] = (float)((double)bn2b[tid] - mq*sc);
    }
    __syncthreads();
    for (int i = tid; i < 8192; i += 1024) {
        int o = i >> 8, w = i & 255;
        float sc = s2sh[o], sh = h2sh[o];
        float4 v = *(const float4*)(g_q + (size_t)(b*32 + o)*QSTRIDE + 4*w);
        float vl[4] = {v.x, v.y, v.z, v.w};
        float s = 0.f;
#pragma unroll
        for (int j = 0; j < 4; j++) {
            float y = fmaf(sc, vl[j], sh);
            s += (y > 0.f) ? y : expm1f(y);
        }
        ps[o*272 + 8 + w] = s * 0.25f;
    }
    __syncthreads();
    // conv1: w in [0,257)
    for (int g = tid; g < 2080; g += 1024) {
        int o = g / 65, w4 = (g - o*65) * 4;
        const float* prow = ps + o*272 + w4;
        float wbuf[8];
        float4 v0 = *(const float4*)(prow);
        float4 v1 = *(const float4*)(prow + 4);
        wbuf[0]=v0.x; wbuf[1]=v0.y; wbuf[2]=v0.z; wbuf[3]=v0.w;
        wbuf[4]=v1.x; wbuf[5]=v1.y; wbuf[6]=v1.z; wbuf[7]=v1.w;
        float a0=0.f,a1=0.f,a2=0.f,a3v=0.f;
#pragma unroll
        for (int k4 = 0; k4 < 4; k4++) {
#pragma unroll
            for (int kk = 0; kk < 4; kk++) {
                float wv = we1[o*16 + 4*k4 + kk];
                a0  = fmaf(wv, wbuf[kk],   a0);
                a1  = fmaf(wv, wbuf[kk+1], a1);
                a2  = fmaf(wv, wbuf[kk+2], a2);
                a3v = fmaf(wv, wbuf[kk+3], a3v);
            }
            if (k4 < 3) {
                float4 nv = *(const float4*)(prow + 8 + 4*k4);
                wbuf[0]=wbuf[4]; wbuf[1]=wbuf[5]; wbuf[2]=wbuf[6]; wbuf[3]=wbuf[7];
                wbuf[4]=nv.x; wbuf[5]=nv.y; wbuf[6]=nv.z; wbuf[7]=nv.w;
            }
        }
        float* q1r = q1 + o*280 + 8 + w4;
        if (w4     < 257) q1r[0] = a0;
        if (w4 + 1 < 257) q1r[1] = a1;
        if (w4 + 2 < 257) q1r[2] = a2;
        if (w4 + 3 < 257) q1r[3] = a3v;
    }
    __syncthreads();
    // conv2: w in [0,258)
    for (int g = tid; g < 2080; g += 1024) {
        int o = g / 65, w4 = (g - o*65) * 4;
        const float* prow = q1 + o*280 + w4;
        float wbuf[8];
        float4 v0 = *(const float4*)(prow);
        float4 v1 = *(const float4*)(prow + 4);
        wbuf[0]=v0.x; wbuf[1]=v0.y; wbuf[2]=v0.z; wbuf[3]=v0.w;
        wbuf[4]=v1.x; wbuf[5]=v1.y; wbuf[6]=v1.z; wbuf[7]=v1.w;
        float a0=0.f,a1=0.f,a2=0.f,a3v=0.f;
#pragma unroll
        for (int k4 = 0; k4 < 4; k4++) {
#pragma unroll
            for (int kk = 0; kk < 4; kk++) {
                float wv = we2[o*16 + 4*k4 + kk];
                a0  = fmaf(wv, wbuf[kk],   a0);
                a1  = fmaf(wv, wbuf[kk+1], a1);
                a2  = fmaf(wv, wbuf[kk+2], a2);
                a3v = fmaf(wv, wbuf[kk+3], a3v);
            }
            if (k4 < 3) {
                float4 nv = *(const float4*)(prow + 8 + 4*k4);
                wbuf[0]=wbuf[4]; wbuf[1]=wbuf[5]; wbuf[2]=wbuf[6]; wbuf[3]=wbuf[7];
                wbuf[4]=nv.x; wbuf[5]=nv.y; wbuf[6]=nv.z; wbuf[7]=nv.w;
            }
        }
        float* q2r = q2 + o*260 + w4;
        if (w4     < 258) q2r[0] = a0;
        if (w4 + 1 < 258) q2r[1] = a1;
        if (w4 + 2 < 258) q2r[2] = a2;
        if (w4 + 3 < 258) q2r[3] = a3v;
    }
    __syncthreads();
    // pointwise 32x32: one channel per warp (32 warps)
    {
        int o = tid >> 5;
        int wslot = tid & 31;
        float ls = 0.f, lq = 0.f;
        for (int it = 0; it < 3; it++) {
            int w4 = 4*(wslot + 32*it);
            if (w4 > 256) continue;
            float a0=0.f,a1=0.f,a2=0.f,a3v=0.f;
#pragma unroll 8
            for (int c = 0; c < 32; c++) {
                float4 qv = *(const float4*)(q2 + c*260 + w4);
                float wv = wpp[o*32 + c];
                a0  = fmaf(wv, qv.x, a0);
                a1  = fmaf(wv, qv.y, a1);
                a2  = fmaf(wv, qv.z, a2);
                a3v = fmaf(wv, qv.w, a3v);
            }
            float* r0 = rr + o*260 + w4;
            int nv = WB - w4;
            if (nv > 0) { r0[0]=a0;  ls+=a0;  lq+=a0*a0; }
            if (nv > 1) { r0[1]=a1;  ls+=a1;  lq+=a1*a1; }
            if (nv > 2) { r0[2]=a2;  ls+=a2;  lq+=a2*a2; }
            if (nv > 3) { r0[3]=a3v; ls+=a3v; lq+=a3v*a3v; }
        }
        for (int d = 16; d > 0; d >>= 1) {
            ls += __shfl_down_sync(0xffffffffu, ls, d);
            lq += __shfl_down_sync(0xffffffffu, lq, d);
        }
        if (wslot == 0) {
            atomicAdd(&g_bn3s[o], (double)ls);
            atomicAdd(&g_bn3q[o], (double)lq);
        }
    }
    grid_barrier(128u);

    // ================= Phase B: bn3+elu+pool+normalize+lift -> pts (sp), domain sums =========
    for (int i = tid; i < 1089; i += 1024) lcw[i] = lc1[i];
    if (tid < 32) {
        double mean = g_bn3s[tid] / NTOT3;
        double var = g_bn3q[tid] / NTOT3 - mean * mean;
        float a = (float)((double)bn3w[tid] / sqrt(var + 1e-3));
        a3[tid] = a;
        c3[tid] = (float)((double)bn3b[tid] - mean * (double)a);
    }
    __syncthreads();
    for (int t = tid; t < 2048; t += 1024) {
        int w = t >> 5, c = t & 31;
        const float* rb = rr + c * 260 + w * 4;
        float acc = 0.f;
#pragma unroll
        for (int i = 0; i < 4; i++) {
            float v = a3[c] * rb[i] + c3[c];
            acc += (v > 0.f) ? v : expm1f(v);
        }
        vv[w * 33 + c] = acc * 0.25f;
    }
    __syncthreads();
    if (tid < 64) {
        int w = tid;
        float ssq = 0.f;
        for (int c = 0; c < 32; c++) { float sv = vv[w*33+c]; ssq += sv * sv; }
        float inv = 1.f / fmaxf(sqrtf(ssq), 1e-12f);
        float hs2 = 0.f;
        for (int c = 0; c < 32; c++) { float sv = vv[w*33+c] * inv; vv[w*33+c] = sv; hs2 += sv * sv; }
        vv[w * 33 + 32] = sqrtf(1.f + hs2);
    }
    __syncthreads();
    for (int t = tid; t < 2048; t += 1024) {
        int w = t >> 5, o = (t & 31) + 1;
        float acc = lcw[o * 33] * vv[w * 33 + 32];
#pragma unroll
        for (int c = 0; c < 32; c++) acc = fmaf(lcw[o * 33 + 1 + c], vv[w * 33 + c], acc);
        sp[w * 33 + o] = acc;
    }
    __syncthreads();
    if (tid < 64) {
        float ysq = 0.f;
        for (int o = 1; o < 33; o++) { float pv = sp[tid*33+o]; ysq += pv * pv; }
        sp[tid * 33] = sqrtf(1.f + ysq);
    }
    __syncthreads();
    if (tid < 33) {
        float acc = 0.f;
        for (int ww = 0; ww < 64; ww++) acc += sp[ww * 33 + tid];
        atomicAdd(&g_sdom[dom * 33 + tid], acc);
    }
    if (tid == 0) atomicAdd(&g_cnt[dom], 64.f);
    grid_barrier(256u);

    // ================= Phase C: mu + log-map + transport, dist^2 (smem-resident) =============
    if (tid < 33) {
        float cnt = fmaxf(g_cnt[dom], 1.f);
        mus[tid] = g_sdom[dom * 33 + tid] / cnt;
    }
    __syncthreads();
    if (tid == 0) {
        float mm = -mus[0] * mus[0];
        for (int j = 1; j < 33; j++) mm += mus[j] * mus[j];
        dnv = sqrtf(fmaxf(fabsf(mm), 1e-8f));
    }
    __syncthreads();
    if (tid < 33) mus[tid] = mus[tid] / dnv;
    __syncthreads();
    if (tid < 64) {
        const float* prow = sp + tid * 33;
        float ip = -mus[0] * prow[0];
        for (int j = 1; j < 33; j++) ip = fmaf(mus[j], prow[j], ip);
        float ci = fmaxf(-ip, 1.f + 1e-7f);
        float dist = acoshf(ci);
        float u0 = prow[0] + ip * mus[0];
        float muu = -u0 * u0;
        for (int j = 1; j < 33; j++) {
            float uj = fmaf(ip, mus[j], prow[j]);
            muu = fmaf(uj, uj, muu);
        }
        float un = sqrtf(fmaxf(muu, 1e-8f));
        float sc = dist / un;
        float v0 = sc * u0;
        float f = -v0 / (1.f + mus[0]);
        vv[tid * 33 + 0] = v0 + f * (mus[0] + 1.f);
        for (int j = 1; j < 33; j++) {
            float uj = fmaf(ip, mus[j], prow[j]);
            vv[tid * 33 + j] = fmaf(sc, uj, f * mus[j]);
        }
        redA[tid] = dist * dist;
    }
    __syncthreads();
    if (tid == 0) {
        float s = 0.f;
        for (int i = 0; i < 64; i++) s += redA[i];
        atomicAdd(&g_dist2[dom], s);
    }
    grid_barrier(384u);

    // ================= Phase D: scale + beta transport + exp-map + elu + pool + out ==========
    if (tid < 33) bs[tid] = beta[tid];
    __syncthreads();
    if (tid < 64) {
        float cnt = fmaxf(g_cnt[dom], 1.f);
        float var = g_dist2[dom] / cnt;
        float scale = gamma[0] / sqrtf(var + 1e-5f);
        const float* vrow = vv + tid * 33;
        float mb = -bs[0] * vrow[0];
        for (int j = 1; j < 33; j++) mb = fmaf(bs[j], vrow[j], mb);
        mb *= scale;
        float f = mb / (1.f + bs[0]);
        float v0 = fmaf(vrow[0], scale, f * (1.f + bs[0]));
        float mv = -v0 * v0;
        for (int j = 1; j < 33; j++) {
            float vj = fmaf(vrow[j], scale, f * bs[j]);
            mv = fmaf(vj, vj, mv);
        }
        float vn = sqrtf(fmaxf(mv, 1e-8f));
        float ch = coshf(vn), sh = sinhf(vn) / vn;
        float ssum = 0.f;
        for (int j = 1; j < 33; j++) {
            float vj = fmaf(vrow[j], scale, f * bs[j]);
            float y = fmaf(ch, bs[j], sh * vj);
            float e = (y > 0.f) ? y : expm1f(y);
            hsm[tid * 33 + j] = e;
            ssum = fmaf(e, e, ssum);
        }
        hsm[tid * 33 + 0] = sqrtf(1.f + ssum);
    }
    __syncthreads();
    if (tid < 16) {
        const float* h0 = hsm + (4 * tid) * 33;
        const float* h1 = hsm + (4 * tid + 1) * 33;
        const float* h2 = hsm + (4 * tid + 2) * 33;
        const float* h3 = hsm + (4 * tid + 3) * 33;
        float m0 = 0.25f * (h0[0] + h1[0] + h2[0] + h3[0]);
        float mm = -m0 * m0;
        for (int j = 1; j < 33; j++) {
            float mj = 0.25f * (h0[j] + h1[j] + h2[j] + h3[j]);
            mm = fmaf(mj, mj, mm);
        }
        float dnm = sqrtf(fmaxf(fabsf(mm), 1e-8f));
        float inv = 1.f / dnm;
        pl[tid * 33] = m0 * inv;
        for (int j = 1; j < 33; j++) {
            float mj = 0.25f * (h0[j] + h1[j] + h2[j] + h3[j]);
            pl[tid * 33 + j] = mj * inv;
        }
    }
    __syncthreads();
    if (tid < 64) {
        float pssq = 0.f, pdot = 0.f, pz2 = 0.f;
        for (int i = tid; i < 512; i += 64) {
            int g = i >> 5, j = (i & 31) + 1;
            float fv = pl[g * 33 + j];
            out[128 + b * 513 + 1 + i] = fv;
            float zv = z[i];
            pssq += fv * fv;
            pdot += fv * zv;
            pz2  += zv * zv;
        }
        redA[tid] = pssq;
        redB[tid] = pdot;
        redC[tid] = pz2;
    }
    __syncthreads();
    if (tid == 0) {
        float ssq = 0.f, dot = 0.f, z2 = 0.f;
        for (int i = 0; i < 64; i++) { ssq += redA[i]; dot += redB[i]; z2 += redC[i]; }
        float ft = sqrtf(1.f + ssq);
        out[128 + b * 513] = ft;
        float a = mlra[0], nz = sqrtf(z2);
        float wt = sinhf(a) * nz;
        float cz = coshf(a) * nz;
        float bet = sqrtf(fmaxf(cz * cz - wt * wt, 1e-8f));
        float alpha = -wt * ft + coshf(a) * dot;
        float dd = fabsf(asinhf(alpha / bet));
        float sg = (alpha > 0.f) ? 1.f : ((alpha < 0.f) ? -1.f : 0.f);
        out[b] = sg * bet * dd;
    }
}

// ------------------- launch -------------------
extern "C" void kernel_launch(void* const* d_in, const int* in_sizes, int n_in,
                              void* d_out, int out_size) {
    const float* x       = (const float*)d_in[0];
    const int*   domains = (const int*)  d_in[1];
    const float* conv1_w = (const float*)d_in[2];
    const float* bn1_w   = (const float*)d_in[3];
    const float* dw_w    = (const float*)d_in[5];
    const float* bn2_w   = (const float*)d_in[6];
    const float* bn2_b   = (const float*)d_in[7];
    const float* ec1_w   = (const float*)d_in[8];
    const float* b2c1_w  = (const float*)d_in[9];
    const float* b2c2_w  = (const float*)d_in[10];
    const float* bn3_w   = (const float*)d_in[11];
    const float* bn3_b   = (const float*)d_in[12];
    const float* lc1_w   = (const float*)d_in[13];
    const float* bn_beta = (const float*)d_in[14];
    const float* bn_gamma= (const float*)d_in[15];
    const float* mlr_a   = (const float*)d_in[16];
    const float* mlr_z   = (const float*)d_in[17];
    float* out = (float*)d_out;

    static int attr_set = 0;
    static cudaStream_t s1 = nullptr;
    static cudaEvent_t ev0 = nullptr, ev1 = nullptr;
    const int SMEM34 = 10944 * 4;
    const int SMEMT  = 28032 * 4;
    if (!attr_set) {
        cudaFuncSetAttribute(k34,   cudaFuncAttributeMaxDynamicSharedMemorySize, SMEM34);
        cudaFuncSetAttribute(ktail, cudaFuncAttributeMaxDynamicSharedMemorySize, SMEMT);
        cudaStreamCreateWithFlags(&s1, cudaStreamNonBlocking);
        cudaEventCreateWithFlags(&ev0, cudaEventDisableTiming);
        cudaEventCreateWithFlags(&ev1, cudaEventDisableTiming);
        attr_set = 1;
    }

    k0_zero<<<1, 256>>>();
    cudaEventRecord(ev0, 0);
    cudaStreamWaitEvent(s1, ev0, 0);
    k1_stats<<<296, 256, 0, s1>>>(x);
    k2_bn1<<<1, 256, 0, s1>>>(conv1_w, bn1_w);
    cudaEventRecord(ev1, s1);
    k34<<<dim3(4, 128), 256, SMEM34>>>(x, dw_w, conv1_w);
    cudaStreamWaitEvent(0, ev1, 0);
    ktail<<<128, 1024, SMEMT>>>(ec1_w, b2c1_w, b2c2_w, bn2_w, bn2_b,
                                bn3_w, bn3_b, lc1_w, domains,
                                bn_beta, bn_gamma, mlr_a, mlr_z, out);
}